// round 1
// baseline (speedup 1.0000x reference)
#include <cuda_runtime.h>
#include <math_constants.h>

// Problem constants (fixed by the dataset)
#define TRAJ        128
#define NNODES      1048576            // 8192 * 128
#define NGRAPH      8192
#define NEDGES_MAX  8388608

// Scratch (static __device__ arrays: allocation-free per harness rules)
__device__ float4 g_scratch[2 * NNODES];   // node i: [2i]={p.xyz, cum_dist}, [2i+1]={dr_.xyz, cum_msd}
__device__ float  g_graphMax[NGRAPH];      // per-graph max of dr_norm
__device__ float  g_fv[NGRAPH];            // dr_norm at first node of graph
__device__ float  g_gpfxFv[NGRAPH];        // exclusive global max prefix + fv

// ---------------------------------------------------------------------------
// Kernel A: per-graph features. 1 block (128 thr) per graph.
// ---------------------------------------------------------------------------
__global__ void __launch_bounds__(128) kernelA(
    const float* __restrict__ P,
    float4* __restrict__ scr,
    float*  __restrict__ X,       // [N,4]
    float*  __restrict__ S,       // [G,2]
    float*  __restrict__ U,       // [G,3]
    float*  __restrict__ gMax,
    float*  __restrict__ gFv)
{
    const int g = blockIdx.x;
    const int t = threadIdx.x;
    const int lane = t & 31;
    const int w = t >> 5;

    __shared__ float4 sP4[96];                 // 128 nodes * 3 floats
    float* sP = (float*)sP4;
    __shared__ float red[4][9];
    __shared__ float wsum[4], wsum2[4], wmax[4];
    __shared__ float s_fv;

    // cooperative coalesced load of this graph's P tile (384 floats)
    const float4* Pg = (const float4*)(P + (size_t)g * (TRAJ * 3));
    if (t < 96) sP4[t] = Pg[t];
    __syncthreads();

    float px = sP[3*t], py = sP[3*t+1], pz = sP[3*t+2];
    float dx = 0.f, dy = 0.f, dz = 0.f;
    if (t < TRAJ - 1) {
        dx = sP[3*t+3] - px;
        dy = sP[3*t+4] - py;
        dz = sP[3*t+5] - pz;
    }

    // 9-value block reduction: sum P, sum P^2, sum dr
    float v[9] = { px, py, pz, px*px, py*py, pz*pz, dx, dy, dz };
    #pragma unroll
    for (int k = 0; k < 9; k++) {
        #pragma unroll
        for (int off = 16; off; off >>= 1)
            v[k] += __shfl_xor_sync(0xffffffffu, v[k], off);
    }
    if (lane == 0) {
        #pragma unroll
        for (int k = 0; k < 9; k++) red[w][k] = v[k];
    }
    __syncthreads();
    float tot[9];
    #pragma unroll
    for (int k = 0; k < 9; k++)
        tot[k] = red[0][k] + red[1][k] + red[2][k] + red[3][k];

    const float invL = 1.0f / (float)TRAJ;
    float mx = tot[0]*invL, my = tot[1]*invL, mz = tot[2]*invL;
    float var = (tot[3]*invL - mx*mx) + (tot[4]*invL - my*my) + (tot[5]*invL - mz*mz);
    float pstd = sqrtf(var);
    float isf = 1.0f / pstd;

    // normalized quantities
    float pnx = px*isf, pny = py*isf, pnz = pz*isf;
    float rdx = dx*isf, rdy = dy*isf, rdz = dz*isf;
    float dn  = sqrtf(1e-5f + rdx*rdx + rdy*rdy + rdz*rdz);
    float dn2 = dn * dn;

    // block inclusive scans: sum(dn), sum(dn2), max(dn)
    float cs = dn, cs2 = dn2, cm = dn;
    #pragma unroll
    for (int off = 1; off < 32; off <<= 1) {
        float a  = __shfl_up_sync(0xffffffffu, cs,  off);
        float a2 = __shfl_up_sync(0xffffffffu, cs2, off);
        float am = __shfl_up_sync(0xffffffffu, cm,  off);
        if (lane >= off) { cs += a; cs2 += a2; cm = fmaxf(cm, am); }
    }
    if (lane == 31) { wsum[w] = cs; wsum2[w] = cs2; wmax[w] = cm; }
    if (t == 0) s_fv = dn;
    __syncthreads();
    float o = 0.f, o2 = 0.f, om = -CUDART_INF_F;
    for (int j = 0; j < w; j++) { o += wsum[j]; o2 += wsum2[j]; om = fmaxf(om, wmax[j]); }
    cs += o; cs2 += o2; cm = fmaxf(cm, om);

    // outputs
    const int i = g * TRAJ + t;
    float tn = (float)(t + 1) * invL;
    float4 xo = make_float4(tn, cs, cs2, cm + s_fv);   // col 3 patched later by kernelC
    ((float4*)X)[i] = xo;

    scr[2*i]     = make_float4(pnx, pny, pnz, cs);
    scr[2*i + 1] = make_float4(rdx, rdy, rdz, cs2);

    if (t == TRAJ - 1) gMax[g] = cm;
    if (t == 0) {
        gFv[g] = dn;
        S[2*g]     = pstd;
        S[2*g + 1] = (float)TRAJ;
        float ux = tot[6]*invL, uy = tot[7]*invL, uz = tot[8]*invL;
        float ui = 1.0f / sqrtf(1e-5f + ux*ux + uy*uy + uz*uz);
        U[3*g]     = ux * ui;
        U[3*g + 1] = uy * ui;
        U[3*g + 2] = uz * ui;
    }
}

// ---------------------------------------------------------------------------
// Kernel B: exclusive max-scan over the 8192 graph maxima; out = gpfx + fv.
// Single block, 256 threads, 32 graphs per thread.
// ---------------------------------------------------------------------------
__global__ void __launch_bounds__(256) kernelB(
    const float* __restrict__ gMax,
    const float* __restrict__ gFv,
    float* __restrict__ out)
{
    const int t = threadIdx.x;
    const int lane = t & 31, w = t >> 5;
    const int CH = NGRAPH / 256;   // 32

    float m = -CUDART_INF_F;
    #pragma unroll 4
    for (int j = 0; j < CH; j++) m = fmaxf(m, gMax[t*CH + j]);

    // inclusive max-scan of chunk maxima across 256 threads
    float x = m;
    #pragma unroll
    for (int off = 1; off < 32; off <<= 1) {
        float a = __shfl_up_sync(0xffffffffu, x, off);
        if (lane >= off) x = fmaxf(x, a);
    }
    __shared__ float wm[8];
    __shared__ float inclA[256];
    if (lane == 31) wm[w] = x;
    __syncthreads();
    float pre = -CUDART_INF_F;
    for (int j = 0; j < w; j++) pre = fmaxf(pre, wm[j]);
    inclA[t] = fmaxf(x, pre);
    __syncthreads();
    float run = (t > 0) ? inclA[t - 1] : -CUDART_INF_F;

    for (int j = 0; j < CH; j++) {
        int idx = t*CH + j;
        out[idx] = run + gFv[idx];
        run = fmaxf(run, gMax[idx]);
    }
}

// ---------------------------------------------------------------------------
// Kernel C: patch X[:,3] with the global-cummax prefix.
// ---------------------------------------------------------------------------
__global__ void __launch_bounds__(128) kernelC(
    float* __restrict__ X, const float* __restrict__ gpfxFv)
{
    const int g = blockIdx.x;
    const float a = __ldg(gpfxFv + g);
    const int i = g * TRAJ + threadIdx.x;
    float4* X4 = (float4*)X;
    float4 vv = X4[i];
    vv.w = fmaxf(vv.w, a);
    X4[i] = vv;
}

// ---------------------------------------------------------------------------
// Kernel D: edge features. 256 edges per block, smem-staged coalesced write.
// ---------------------------------------------------------------------------
__global__ void __launch_bounds__(256) kernelD(
    const int* __restrict__ row,
    const int* __restrict__ col,
    const float4* __restrict__ scr,
    float* __restrict__ Eo,
    int Ecount)
{
    __shared__ float4 sm4[320];          // 256 edges * 5 floats
    float* sm = (float*)sm4;
    const int t = threadIdx.x;
    const int base = blockIdx.x * 256;
    const int e = base + t;

    float f0 = 0.f, f1 = 0.f, f2 = 0.f, f3 = 0.f, f4 = 0.f;
    if (e < Ecount) {
        int r = __ldg(row + e);
        int c = __ldg(col + e);
        float4 ar = __ldg(scr + 2*r);
        float4 br = __ldg(scr + 2*r + 1);
        float4 ac = __ldg(scr + 2*c);
        float4 bc = __ldg(scr + 2*c + 1);
        f0 = (float)((r & (TRAJ-1)) - (c & (TRAJ-1))) * (1.0f / (float)TRAJ);
        float ddx = ar.x - ac.x, ddy = ar.y - ac.y, ddz = ar.z - ac.z;
        f1 = sqrtf(ddx*ddx + ddy*ddy + ddz*ddz);
        f2 = br.x*bc.x + br.y*bc.y + br.z*bc.z;
        f3 = ar.w - ac.w;
        f4 = br.w - bc.w;
    }
    sm[t*5 + 0] = f0;
    sm[t*5 + 1] = f1;
    sm[t*5 + 2] = f2;
    sm[t*5 + 3] = f3;
    sm[t*5 + 4] = f4;
    __syncthreads();

    int nvalid = Ecount - base;
    if (nvalid >= 256) {
        float4* dst = (float4*)(Eo + (size_t)base * 5);
        #pragma unroll
        for (int j = t; j < 320; j += 256) dst[j] = sm4[j];
    } else if (nvalid > 0) {
        int nf = nvalid * 5;
        for (int j = t; j < nf; j += 256) Eo[(size_t)base * 5 + j] = sm[j];
    }
}

// ---------------------------------------------------------------------------
extern "C" void kernel_launch(void* const* d_in, const int* in_sizes, int n_in,
                              void* d_out, int out_size)
{
    const float* P   = (const float*)d_in[0];
    // d_in[1] = B (implied by i/128, unused)
    const int*   row = (const int*)d_in[2];
    const int*   col = (const int*)d_in[3];

    const int N = in_sizes[0] / 3;        // 1,048,576
    const int G = N / TRAJ;               // 8,192
    const int E = in_sizes[2];            // 8,388,608

    float* out = (float*)d_out;
    float* X  = out;                       // [N,4]
    float* Eo = out + (size_t)4 * N;       // [E,5]
    float* S  = Eo + (size_t)5 * E;        // [G,2]
    float* U  = S + (size_t)2 * G;         // [G,3]

    float4* scr;   cudaGetSymbolAddress((void**)&scr,   g_scratch);
    float*  gMax;  cudaGetSymbolAddress((void**)&gMax,  g_graphMax);
    float*  gFv;   cudaGetSymbolAddress((void**)&gFv,   g_fv);
    float*  gPfx;  cudaGetSymbolAddress((void**)&gPfx,  g_gpfxFv);

    kernelA<<<G, 128>>>(P, scr, X, S, U, gMax, gFv);
    kernelB<<<1, 256>>>(gMax, gFv, gPfx);
    kernelC<<<G, 128>>>(X, gPfx);
    kernelD<<<(E + 255) / 256, 256>>>(row, col, scr, Eo, E);
}

// round 2
// speedup vs baseline: 1.1746x; 1.1746x over previous
#include <cuda_runtime.h>
#include <math_constants.h>

// Problem constants (fixed by the dataset)
#define TRAJ        128
#define NNODES      1048576            // 8192 * 128
#define NGRAPH      8192
#define NEDGES_MAX  8388608

// Scratch (static __device__ arrays: allocation-free per harness rules)
__device__ float4 g_scratch[2 * NNODES];   // node i: [2i]={p.xyz, cum_dist}, [2i+1]={dr_.xyz, cum_msd}
__device__ float  g_graphMax[NGRAPH];      // per-graph max of dr_norm
__device__ float  g_fv[NGRAPH];            // dr_norm at first node of graph
__device__ float  g_gpfxFv[NGRAPH];        // exclusive global max prefix + fv

// ---------------------------------------------------------------------------
// Kernel A: per-graph features. 1 block (128 thr) per graph.
// ---------------------------------------------------------------------------
__global__ void __launch_bounds__(128) kernelA(
    const float* __restrict__ P,
    float4* __restrict__ scr,
    float*  __restrict__ X,       // [N,4]
    float*  __restrict__ S,       // [G,2]
    float*  __restrict__ U,       // [G,3]
    float*  __restrict__ gMax,
    float*  __restrict__ gFv)
{
    const int g = blockIdx.x;
    const int t = threadIdx.x;
    const int lane = t & 31;
    const int w = t >> 5;

    __shared__ float4 sP4[96];                 // 128 nodes * 3 floats
    float* sP = (float*)sP4;
    __shared__ float red[4][9];
    __shared__ float wsum[4], wsum2[4], wmax[4];
    __shared__ float s_fv;

    // cooperative coalesced load of this graph's P tile (384 floats)
    const float4* Pg = (const float4*)(P + (size_t)g * (TRAJ * 3));
    if (t < 96) sP4[t] = Pg[t];
    __syncthreads();

    float px = sP[3*t], py = sP[3*t+1], pz = sP[3*t+2];
    float dx = 0.f, dy = 0.f, dz = 0.f;
    if (t < TRAJ - 1) {
        dx = sP[3*t+3] - px;
        dy = sP[3*t+4] - py;
        dz = sP[3*t+5] - pz;
    }

    // 9-value block reduction: sum P, sum P^2, sum dr
    float v[9] = { px, py, pz, px*px, py*py, pz*pz, dx, dy, dz };
    #pragma unroll
    for (int k = 0; k < 9; k++) {
        #pragma unroll
        for (int off = 16; off; off >>= 1)
            v[k] += __shfl_xor_sync(0xffffffffu, v[k], off);
    }
    if (lane == 0) {
        #pragma unroll
        for (int k = 0; k < 9; k++) red[w][k] = v[k];
    }
    __syncthreads();
    float tot[9];
    #pragma unroll
    for (int k = 0; k < 9; k++)
        tot[k] = red[0][k] + red[1][k] + red[2][k] + red[3][k];

    const float invL = 1.0f / (float)TRAJ;
    float mx = tot[0]*invL, my = tot[1]*invL, mz = tot[2]*invL;
    float var = (tot[3]*invL - mx*mx) + (tot[4]*invL - my*my) + (tot[5]*invL - mz*mz);
    float pstd = sqrtf(var);
    float isf = 1.0f / pstd;

    // normalized quantities
    float pnx = px*isf, pny = py*isf, pnz = pz*isf;
    float rdx = dx*isf, rdy = dy*isf, rdz = dz*isf;
    float dn  = sqrtf(1e-5f + rdx*rdx + rdy*rdy + rdz*rdz);
    float dn2 = dn * dn;

    // block inclusive scans: sum(dn), sum(dn2), max(dn)
    float cs = dn, cs2 = dn2, cm = dn;
    #pragma unroll
    for (int off = 1; off < 32; off <<= 1) {
        float a  = __shfl_up_sync(0xffffffffu, cs,  off);
        float a2 = __shfl_up_sync(0xffffffffu, cs2, off);
        float am = __shfl_up_sync(0xffffffffu, cm,  off);
        if (lane >= off) { cs += a; cs2 += a2; cm = fmaxf(cm, am); }
    }
    if (lane == 31) { wsum[w] = cs; wsum2[w] = cs2; wmax[w] = cm; }
    if (t == 0) s_fv = dn;
    __syncthreads();
    float o = 0.f, o2 = 0.f, om = -CUDART_INF_F;
    for (int j = 0; j < w; j++) { o += wsum[j]; o2 += wsum2[j]; om = fmaxf(om, wmax[j]); }
    cs += o; cs2 += o2; cm = fmaxf(cm, om);

    // outputs
    const int i = g * TRAJ + t;
    float tn = (float)(t + 1) * invL;
    float4 xo = make_float4(tn, cs, cs2, cm + s_fv);   // col 3 patched later by kernelC
    ((float4*)X)[i] = xo;

    scr[2*i]     = make_float4(pnx, pny, pnz, cs);
    scr[2*i + 1] = make_float4(rdx, rdy, rdz, cs2);

    if (t == TRAJ - 1) gMax[g] = cm;
    if (t == 0) {
        gFv[g] = dn;
        S[2*g]     = pstd;
        S[2*g + 1] = (float)TRAJ;
        float ux = tot[6]*invL, uy = tot[7]*invL, uz = tot[8]*invL;
        float ui = 1.0f / sqrtf(1e-5f + ux*ux + uy*uy + uz*uz);
        U[3*g]     = ux * ui;
        U[3*g + 1] = uy * ui;
        U[3*g + 2] = uz * ui;
    }
}

// ---------------------------------------------------------------------------
// Kernel B: exclusive max-scan over the 8192 graph maxima; out = gpfx + fv.
// ---------------------------------------------------------------------------
__global__ void __launch_bounds__(256) kernelB(
    const float* __restrict__ gMax,
    const float* __restrict__ gFv,
    float* __restrict__ out)
{
    const int t = threadIdx.x;
    const int lane = t & 31, w = t >> 5;
    const int CH = NGRAPH / 256;   // 32

    float m = -CUDART_INF_F;
    #pragma unroll 4
    for (int j = 0; j < CH; j++) m = fmaxf(m, gMax[t*CH + j]);

    // inclusive max-scan of chunk maxima across 256 threads
    float x = m;
    #pragma unroll
    for (int off = 1; off < 32; off <<= 1) {
        float a = __shfl_up_sync(0xffffffffu, x, off);
        if (lane >= off) x = fmaxf(x, a);
    }
    __shared__ float wm[8];
    __shared__ float inclA[256];
    if (lane == 31) wm[w] = x;
    __syncthreads();
    float pre = -CUDART_INF_F;
    for (int j = 0; j < w; j++) pre = fmaxf(pre, wm[j]);
    inclA[t] = fmaxf(x, pre);
    __syncthreads();
    float run = (t > 0) ? inclA[t - 1] : -CUDART_INF_F;

    for (int j = 0; j < CH; j++) {
        int idx = t*CH + j;
        out[idx] = run + gFv[idx];
        run = fmaxf(run, gMax[idx]);
    }
}

// ---------------------------------------------------------------------------
// Kernel C: patch X[:,3] with the global-cummax prefix.
// ---------------------------------------------------------------------------
__global__ void __launch_bounds__(128) kernelC(
    float* __restrict__ X, const float* __restrict__ gpfxFv)
{
    const int g = blockIdx.x;
    const float a = __ldg(gpfxFv + g);
    const int i = g * TRAJ + threadIdx.x;
    float4* X4 = (float4*)X;
    float4 vv = X4[i];
    vv.w = fmaxf(vv.w, a);
    X4[i] = vv;
}

// ---------------------------------------------------------------------------
// Kernel D: edge features, lane-pair cooperative gather.
//
// Each edge endpoint owns 32B = {scr[2i], scr[2i+1]}, which always sits in a
// single 128B line. A lane PAIR (2k, 2k+1) loads both halves of one endpoint
// in the SAME LDG.128 instruction -> the two lanes coalesce to ONE L1
// wavefront (vs two in the naive per-thread scheme). The feature set splits
// cleanly: half h=0 ({p, cum_dist}) computes d and delta-cum_dist; half h=1
// ({dr_, cum_msd}) computes corr and delta-cum_msd. No shuffles needed.
// ---------------------------------------------------------------------------
__global__ void __launch_bounds__(256) kernelD(
    const int* __restrict__ row,
    const int* __restrict__ col,
    const float4* __restrict__ scr,
    float* __restrict__ Eo,
    int Ecount)
{
    __shared__ float4 sm4[320];          // 256 edges * 5 floats
    float* sm = (float*)sm4;
    const int t = threadIdx.x;
    const int warp = t >> 5;
    const int lane = t & 31;
    const int k = lane >> 1;             // pair index 0..15
    const int h = lane & 1;              // half selector
    const int base = blockIdx.x * 256;

    #pragma unroll
    for (int half = 0; half < 2; half++) {
        const int eb = warp * 32 + half * 16 + k;    // edge idx within block
        const int e  = base + eb;
        float fa = 0.f, fb = 0.f, f0 = 0.f;
        if (e < Ecount) {
            const int r = __ldg(row + e);
            const int c = __ldg(col + e);
            // lanes 2k and 2k+1 access adjacent float4s of the same endpoint
            // within one instruction -> one wavefront per endpoint.
            float4 Ar = __ldg(scr + 2*r + h);
            float4 Ac = __ldg(scr + 2*c + h);
            if (h == 0) {
                float ddx = Ar.x - Ac.x, ddy = Ar.y - Ac.y, ddz = Ar.z - Ac.z;
                fa = sqrtf(ddx*ddx + ddy*ddy + ddz*ddz);          // d
            } else {
                fa = Ar.x*Ac.x + Ar.y*Ac.y + Ar.z*Ac.z;           // corr
            }
            fb = Ar.w - Ac.w;     // h=0: d_cum_dist, h=1: d_cum_msd
            f0 = (float)((r & (TRAJ-1)) - (c & (TRAJ-1))) * (1.0f / (float)TRAJ);
        }
        if (h == 0) {
            sm[eb*5 + 0] = f0;
            sm[eb*5 + 1] = fa;
            sm[eb*5 + 3] = fb;
        } else {
            sm[eb*5 + 2] = fa;
            sm[eb*5 + 4] = fb;
        }
    }
    __syncthreads();

    const int nvalid = Ecount - base;
    if (nvalid >= 256) {
        float4* dst = (float4*)(Eo + (size_t)base * 5);
        #pragma unroll
        for (int j = t; j < 320; j += 256) dst[j] = sm4[j];
    } else if (nvalid > 0) {
        const int nf = nvalid * 5;
        for (int j = t; j < nf; j += 256) Eo[(size_t)base * 5 + j] = sm[j];
    }
}

// ---------------------------------------------------------------------------
extern "C" void kernel_launch(void* const* d_in, const int* in_sizes, int n_in,
                              void* d_out, int out_size)
{
    const float* P   = (const float*)d_in[0];
    // d_in[1] = B (implied by i/128, unused)
    const int*   row = (const int*)d_in[2];
    const int*   col = (const int*)d_in[3];

    const int N = in_sizes[0] / 3;        // 1,048,576
    const int G = N / TRAJ;               // 8,192
    const int E = in_sizes[2];            // 8,388,608

    float* out = (float*)d_out;
    float* X  = out;                       // [N,4]
    float* Eo = out + (size_t)4 * N;       // [E,5]
    float* S  = Eo + (size_t)5 * E;        // [G,2]
    float* U  = S + (size_t)2 * G;         // [G,3]

    float4* scr;   cudaGetSymbolAddress((void**)&scr,   g_scratch);
    float*  gMax;  cudaGetSymbolAddress((void**)&gMax,  g_graphMax);
    float*  gFv;   cudaGetSymbolAddress((void**)&gFv,   g_fv);
    float*  gPfx;  cudaGetSymbolAddress((void**)&gPfx,  g_gpfxFv);

    kernelA<<<G, 128>>>(P, scr, X, S, U, gMax, gFv);
    kernelB<<<1, 256>>>(gMax, gFv, gPfx);
    kernelC<<<G, 128>>>(X, gPfx);
    kernelD<<<(E + 255) / 256, 256>>>(row, col, scr, Eo, E);
}

// round 3
// speedup vs baseline: 1.3195x; 1.1233x over previous
#include <cuda_runtime.h>
#include <math_constants.h>

#define TRAJ        128
#define NNODES      1048576
#define NGRAPH      8192

__device__ float4 g_scratch[2 * NNODES];   // node i: [2i]={p.xyz, cum_dist}, [2i+1]={dr_.xyz, cum_msd}
__device__ float  g_cm[NNODES];            // local (within-graph) cummax of dr_norm
__device__ float  g_graphMax[NGRAPH];
__device__ float  g_fv[NGRAPH];            // dr_norm at first node of graph
__device__ float  g_gpfx[NGRAPH];          // exclusive global max prefix (pure, no fv)

// ---------------------------------------------------------------------------
// Kernel A: per-graph features. 1 block (128 thr) per graph. Does NOT write X.
// ---------------------------------------------------------------------------
__global__ void __launch_bounds__(128) kernelA(
    const float* __restrict__ P,
    float4* __restrict__ scr,
    float*  __restrict__ cmOut,
    float*  __restrict__ S,
    float*  __restrict__ U,
    float*  __restrict__ gMax,
    float*  __restrict__ gFv)
{
    const int g = blockIdx.x;
    const int t = threadIdx.x;
    const int lane = t & 31;
    const int w = t >> 5;

    __shared__ float4 sP4[96];
    float* sP = (float*)sP4;
    __shared__ float red[4][9];
    __shared__ float wsum[4], wsum2[4], wmax[4];

    const float4* Pg = (const float4*)(P + (size_t)g * (TRAJ * 3));
    if (t < 96) sP4[t] = Pg[t];
    __syncthreads();

    float px = sP[3*t], py = sP[3*t+1], pz = sP[3*t+2];
    float dx = 0.f, dy = 0.f, dz = 0.f;
    if (t < TRAJ - 1) {
        dx = sP[3*t+3] - px;
        dy = sP[3*t+4] - py;
        dz = sP[3*t+5] - pz;
    }

    float v[9] = { px, py, pz, px*px, py*py, pz*pz, dx, dy, dz };
    #pragma unroll
    for (int k = 0; k < 9; k++) {
        #pragma unroll
        for (int off = 16; off; off >>= 1)
            v[k] += __shfl_xor_sync(0xffffffffu, v[k], off);
    }
    if (lane == 0) {
        #pragma unroll
        for (int k = 0; k < 9; k++) red[w][k] = v[k];
    }
    __syncthreads();
    float tot[9];
    #pragma unroll
    for (int k = 0; k < 9; k++)
        tot[k] = red[0][k] + red[1][k] + red[2][k] + red[3][k];

    const float invL = 1.0f / (float)TRAJ;
    float mx = tot[0]*invL, my = tot[1]*invL, mz = tot[2]*invL;
    float var = (tot[3]*invL - mx*mx) + (tot[4]*invL - my*my) + (tot[5]*invL - mz*mz);
    float pstd = sqrtf(var);
    float isf = 1.0f / pstd;

    float pnx = px*isf, pny = py*isf, pnz = pz*isf;
    float rdx = dx*isf, rdy = dy*isf, rdz = dz*isf;
    float dn  = sqrtf(1e-5f + rdx*rdx + rdy*rdy + rdz*rdz);
    float dn2 = dn * dn;

    float cs = dn, cs2 = dn2, cm = dn;
    #pragma unroll
    for (int off = 1; off < 32; off <<= 1) {
        float a  = __shfl_up_sync(0xffffffffu, cs,  off);
        float a2 = __shfl_up_sync(0xffffffffu, cs2, off);
        float am = __shfl_up_sync(0xffffffffu, cm,  off);
        if (lane >= off) { cs += a; cs2 += a2; cm = fmaxf(cm, am); }
    }
    if (lane == 31) { wsum[w] = cs; wsum2[w] = cs2; wmax[w] = cm; }
    __syncthreads();
    float o = 0.f, o2 = 0.f, om = -CUDART_INF_F;
    for (int j = 0; j < w; j++) { o += wsum[j]; o2 += wsum2[j]; om = fmaxf(om, wmax[j]); }
    cs += o; cs2 += o2; cm = fmaxf(cm, om);

    const int i = g * TRAJ + t;
    scr[2*i]     = make_float4(pnx, pny, pnz, cs);
    scr[2*i + 1] = make_float4(rdx, rdy, rdz, cs2);
    cmOut[i] = cm;

    if (t == TRAJ - 1) gMax[g] = cm;
    if (t == 0) {
        gFv[g] = dn;
        S[2*g]     = pstd;
        S[2*g + 1] = (float)TRAJ;
        float ux = tot[6]*invL, uy = tot[7]*invL, uz = tot[8]*invL;
        float ui = 1.0f / sqrtf(1e-5f + ux*ux + uy*uy + uz*uz);
        U[3*g]     = ux * ui;
        U[3*g + 1] = uy * ui;
        U[3*g + 2] = uz * ui;
    }
}

// ---------------------------------------------------------------------------
// Kernel B: exclusive max-scan over 8192 graph maxima (pure prefix, no fv).
// 1 block x 1024 threads, 8 graphs per thread.
// ---------------------------------------------------------------------------
__global__ void __launch_bounds__(1024) kernelB(
    const float* __restrict__ gMax,
    float* __restrict__ out)
{
    const int t = threadIdx.x;
    const int lane = t & 31, w = t >> 5;
    const int CH = NGRAPH / 1024;   // 8

    float vals[8];
    float m = -CUDART_INF_F;
    #pragma unroll
    for (int j = 0; j < CH; j++) { vals[j] = gMax[t*CH + j]; m = fmaxf(m, vals[j]); }

    // inclusive warp scan of chunk maxima
    float x = m;
    #pragma unroll
    for (int off = 1; off < 32; off <<= 1) {
        float a = __shfl_up_sync(0xffffffffu, x, off);
        if (lane >= off) x = fmaxf(x, a);
    }
    float e_in_warp = __shfl_up_sync(0xffffffffu, x, 1);
    if (lane == 0) e_in_warp = -CUDART_INF_F;

    __shared__ float wm[32];
    __shared__ float wme[32];
    if (lane == 31) wm[w] = x;
    __syncthreads();
    if (w == 0) {
        float y = wm[lane];
        #pragma unroll
        for (int off = 1; off < 32; off <<= 1) {
            float a = __shfl_up_sync(0xffffffffu, y, off);
            if (lane >= off) y = fmaxf(y, a);
        }
        float ex = __shfl_up_sync(0xffffffffu, y, 1);
        if (lane == 0) ex = -CUDART_INF_F;
        wme[lane] = ex;
    }
    __syncthreads();

    float run = fmaxf(wme[w], e_in_warp);
    #pragma unroll
    for (int j = 0; j < CH; j++) {
        out[t*CH + j] = run;
        run = fmaxf(run, vals[j]);
    }
}

// ---------------------------------------------------------------------------
// Kernel C: compose X entirely (no prior X pass). 512 thr = 4 graphs / block.
// ---------------------------------------------------------------------------
__global__ void __launch_bounds__(512) kernelC(
    const float4* __restrict__ scr,
    const float*  __restrict__ cmIn,
    const float*  __restrict__ gpfx,
    const float*  __restrict__ gFv,
    float* __restrict__ X)
{
    const int t = threadIdx.x;
    const int i = blockIdx.x * 512 + t;
    const int g = i >> 7;
    const int tt = i & (TRAJ - 1);

    float cm  = cmIn[i];
    float gp  = __ldg(gpfx + g);
    float fv  = __ldg(gFv + g);
    float4 a  = __ldg(scr + 2*i);
    float4 b  = __ldg(scr + 2*i + 1);

    float4 xo = make_float4((float)(tt + 1) * (1.0f / (float)TRAJ),
                            a.w, b.w, fmaxf(cm, gp) + fv);
    __stcs(((float4*)X) + i, xo);
}

// ---------------------------------------------------------------------------
// Kernel D: edge features, lane-pair cooperative gather, 512 edges/block.
// __ldcs on indices + __stcs on E keep the 32MB scr table L2-resident.
// ---------------------------------------------------------------------------
__global__ void __launch_bounds__(256, 4) kernelD(
    const int* __restrict__ row,
    const int* __restrict__ col,
    const float4* __restrict__ scr,
    float* __restrict__ Eo,
    int Ecount)
{
    __shared__ float4 sm4[640];          // 512 edges * 5 floats
    float* sm = (float*)sm4;
    const int t = threadIdx.x;
    const int warp = t >> 5;
    const int lane = t & 31;
    const int k = lane >> 1;             // pair index 0..15
    const int h = lane & 1;              // half selector
    const int base = blockIdx.x * 512;

    #pragma unroll
    for (int pass = 0; pass < 4; pass++) {
        const int eb = warp * 64 + pass * 16 + k;
        const int e  = base + eb;
        float fa = 0.f, fb = 0.f, f0 = 0.f;
        if (e < Ecount) {
            const int r = __ldcs(row + e);
            const int c = __ldcs(col + e);
            // lanes 2k,2k+1 hit adjacent float4s of one endpoint's 128B line
            // in the same instruction -> one wavefront per endpoint.
            float4 Ar = __ldg(scr + 2*r + h);
            float4 Ac = __ldg(scr + 2*c + h);
            if (h == 0) {
                float ddx = Ar.x - Ac.x, ddy = Ar.y - Ac.y, ddz = Ar.z - Ac.z;
                fa = sqrtf(ddx*ddx + ddy*ddy + ddz*ddz);          // d
            } else {
                fa = Ar.x*Ac.x + Ar.y*Ac.y + Ar.z*Ac.z;           // corr
            }
            fb = Ar.w - Ac.w;     // h=0: d_cum_dist, h=1: d_cum_msd
            f0 = (float)((r & (TRAJ-1)) - (c & (TRAJ-1))) * (1.0f / (float)TRAJ);
        }
        if (h == 0) {
            sm[eb*5 + 0] = f0;
            sm[eb*5 + 1] = fa;
            sm[eb*5 + 3] = fb;
        } else {
            sm[eb*5 + 2] = fa;
            sm[eb*5 + 4] = fb;
        }
    }
    __syncthreads();

    const int nvalid = Ecount - base;
    if (nvalid >= 512) {
        float4* dst = (float4*)(Eo + (size_t)base * 5);
        #pragma unroll
        for (int j = t; j < 640; j += 256) __stcs(dst + j, sm4[j]);
    } else if (nvalid > 0) {
        const int nf = nvalid * 5;
        for (int j = t; j < nf; j += 256) __stcs(Eo + (size_t)base * 5 + j, sm[j]);
    }
}

// ---------------------------------------------------------------------------
extern "C" void kernel_launch(void* const* d_in, const int* in_sizes, int n_in,
                              void* d_out, int out_size)
{
    const float* P   = (const float*)d_in[0];
    const int*   row = (const int*)d_in[2];
    const int*   col = (const int*)d_in[3];

    const int N = in_sizes[0] / 3;
    const int G = N / TRAJ;
    const int E = in_sizes[2];

    float* out = (float*)d_out;
    float* X  = out;                       // [N,4]
    float* Eo = out + (size_t)4 * N;       // [E,5]
    float* S  = Eo + (size_t)5 * E;        // [G,2]
    float* U  = S + (size_t)2 * G;         // [G,3]

    float4* scr;  cudaGetSymbolAddress((void**)&scr,  g_scratch);
    float*  cm;   cudaGetSymbolAddress((void**)&cm,   g_cm);
    float*  gMax; cudaGetSymbolAddress((void**)&gMax, g_graphMax);
    float*  gFv;  cudaGetSymbolAddress((void**)&gFv,  g_fv);
    float*  gPfx; cudaGetSymbolAddress((void**)&gPfx, g_gpfx);

    kernelA<<<G, 128>>>(P, scr, cm, S, U, gMax, gFv);
    kernelB<<<1, 1024>>>(gMax, gPfx);
    kernelC<<<N / 512, 512>>>(scr, cm, gPfx, gFv, X);
    kernelD<<<(E + 511) / 512, 256>>>(row, col, scr, Eo, E);
}

// round 5
// speedup vs baseline: 1.3245x; 1.0039x over previous
#include <cuda_runtime.h>
#include <math_constants.h>
#include <cstdint>

#define TRAJ        128
#define NNODES      1048576
#define NGRAPH      8192

__device__ float4 g_scratch[2 * NNODES];   // node i: [2i]={p.xyz, cum_dist}, [2i+1]={dr_.xyz, cum_msd}
__device__ float2 g_aux[NNODES];           // {cum_dist, cum_msd} compact copy for kernelC
__device__ float  g_cm[NNODES];            // local (within-graph) cummax of dr_norm
__device__ float  g_graphMax[NGRAPH];
__device__ float  g_fv[NGRAPH];            // dr_norm at first node of graph
__device__ float  g_gpfx[NGRAPH];          // exclusive global max prefix (pure, no fv)

// ---------------------------------------------------------------------------
// Kernel A: per-graph features. 1 block (128 thr) per graph.
// ---------------------------------------------------------------------------
__global__ void __launch_bounds__(128) kernelA(
    const float* __restrict__ P,
    float4* __restrict__ scr,
    float2* __restrict__ aux,
    float*  __restrict__ cmOut,
    float*  __restrict__ S,
    float*  __restrict__ U,
    float*  __restrict__ gMax,
    float*  __restrict__ gFv)
{
    const int g = blockIdx.x;
    const int t = threadIdx.x;
    const int lane = t & 31;
    const int w = t >> 5;

    __shared__ float4 sP4[96];
    float* sP = (float*)sP4;
    __shared__ float red[4][9];
    __shared__ float wsum[4], wsum2[4], wmax[4];

    const float4* Pg = (const float4*)(P + (size_t)g * (TRAJ * 3));
    if (t < 96) sP4[t] = Pg[t];
    __syncthreads();

    float px = sP[3*t], py = sP[3*t+1], pz = sP[3*t+2];
    float dx = 0.f, dy = 0.f, dz = 0.f;
    if (t < TRAJ - 1) {
        dx = sP[3*t+3] - px;
        dy = sP[3*t+4] - py;
        dz = sP[3*t+5] - pz;
    }

    float v[9] = { px, py, pz, px*px, py*py, pz*pz, dx, dy, dz };
    #pragma unroll
    for (int k = 0; k < 9; k++) {
        #pragma unroll
        for (int off = 16; off; off >>= 1)
            v[k] += __shfl_xor_sync(0xffffffffu, v[k], off);
    }
    if (lane == 0) {
        #pragma unroll
        for (int k = 0; k < 9; k++) red[w][k] = v[k];
    }
    __syncthreads();
    float tot[9];
    #pragma unroll
    for (int k = 0; k < 9; k++)
        tot[k] = red[0][k] + red[1][k] + red[2][k] + red[3][k];

    const float invL = 1.0f / (float)TRAJ;
    float mx = tot[0]*invL, my = tot[1]*invL, mz = tot[2]*invL;
    float var = (tot[3]*invL - mx*mx) + (tot[4]*invL - my*my) + (tot[5]*invL - mz*mz);
    float pstd = sqrtf(var);
    float isf = 1.0f / pstd;

    float pnx = px*isf, pny = py*isf, pnz = pz*isf;
    float rdx = dx*isf, rdy = dy*isf, rdz = dz*isf;
    float dn  = sqrtf(1e-5f + rdx*rdx + rdy*rdy + rdz*rdz);
    float dn2 = dn * dn;

    float cs = dn, cs2 = dn2, cm = dn;
    #pragma unroll
    for (int off = 1; off < 32; off <<= 1) {
        float a  = __shfl_up_sync(0xffffffffu, cs,  off);
        float a2 = __shfl_up_sync(0xffffffffu, cs2, off);
        float am = __shfl_up_sync(0xffffffffu, cm,  off);
        if (lane >= off) { cs += a; cs2 += a2; cm = fmaxf(cm, am); }
    }
    if (lane == 31) { wsum[w] = cs; wsum2[w] = cs2; wmax[w] = cm; }
    __syncthreads();
    float o = 0.f, o2 = 0.f, om = -CUDART_INF_F;
    for (int j = 0; j < w; j++) { o += wsum[j]; o2 += wsum2[j]; om = fmaxf(om, wmax[j]); }
    cs += o; cs2 += o2; cm = fmaxf(cm, om);

    const int i = g * TRAJ + t;
    scr[2*i]     = make_float4(pnx, pny, pnz, cs);
    scr[2*i + 1] = make_float4(rdx, rdy, rdz, cs2);
    aux[i]   = make_float2(cs, cs2);
    cmOut[i] = cm;

    if (t == TRAJ - 1) gMax[g] = cm;
    if (t == 0) {
        gFv[g] = dn;
        S[2*g]     = pstd;
        S[2*g + 1] = (float)TRAJ;
        float ux = tot[6]*invL, uy = tot[7]*invL, uz = tot[8]*invL;
        float ui = 1.0f / sqrtf(1e-5f + ux*ux + uy*uy + uz*uz);
        U[3*g]     = ux * ui;
        U[3*g + 1] = uy * ui;
        U[3*g + 2] = uz * ui;
    }
}

// ---------------------------------------------------------------------------
// Kernel B: exclusive max-scan over 8192 graph maxima (pure prefix).
// ---------------------------------------------------------------------------
__global__ void __launch_bounds__(1024) kernelB(
    const float* __restrict__ gMax,
    float* __restrict__ out)
{
    const int t = threadIdx.x;
    const int lane = t & 31, w = t >> 5;
    const int CH = NGRAPH / 1024;   // 8

    float vals[8];
    float m = -CUDART_INF_F;
    #pragma unroll
    for (int j = 0; j < CH; j++) { vals[j] = gMax[t*CH + j]; m = fmaxf(m, vals[j]); }

    float x = m;
    #pragma unroll
    for (int off = 1; off < 32; off <<= 1) {
        float a = __shfl_up_sync(0xffffffffu, x, off);
        if (lane >= off) x = fmaxf(x, a);
    }
    float e_in_warp = __shfl_up_sync(0xffffffffu, x, 1);
    if (lane == 0) e_in_warp = -CUDART_INF_F;

    __shared__ float wm[32];
    __shared__ float wme[32];
    if (lane == 31) wm[w] = x;
    __syncthreads();
    if (w == 0) {
        float y = wm[lane];
        #pragma unroll
        for (int off = 1; off < 32; off <<= 1) {
            float a = __shfl_up_sync(0xffffffffu, y, off);
            if (lane >= off) y = fmaxf(y, a);
        }
        float ex = __shfl_up_sync(0xffffffffu, y, 1);
        if (lane == 0) ex = -CUDART_INF_F;
        wme[lane] = ex;
    }
    __syncthreads();

    float run = fmaxf(wme[w], e_in_warp);
    #pragma unroll
    for (int j = 0; j < CH; j++) {
        out[t*CH + j] = run;
        run = fmaxf(run, vals[j]);
    }
}

// ---------------------------------------------------------------------------
// Kernel C: compose X from compact aux (12MB in, 16MB out).
// ---------------------------------------------------------------------------
__global__ void __launch_bounds__(512) kernelC(
    const float2* __restrict__ aux,
    const float*  __restrict__ cmIn,
    const float*  __restrict__ gpfx,
    const float*  __restrict__ gFv,
    float* __restrict__ X)
{
    const int t = threadIdx.x;
    const int i = blockIdx.x * 512 + t;
    const int g = i >> 7;
    const int tt = i & (TRAJ - 1);

    float cm  = cmIn[i];
    float gp  = __ldg(gpfx + g);
    float fv  = __ldg(gFv + g);
    float2 ab = __ldg(aux + i);

    float4 xo = make_float4((float)(tt + 1) * (1.0f / (float)TRAJ),
                            ab.x, ab.y, fmaxf(cm, gp) + fv);
    __stcs(((float4*)X) + i, xo);
}

// ---------------------------------------------------------------------------
// Kernel D: edge features. Lane-pair gather (1 L1 wavefront per endpoint),
// smem AoS staging, and a single cp.async.bulk TMA store per block so the
// readback+store leaves the per-lane L1 pipe entirely.
// ---------------------------------------------------------------------------
__global__ void __launch_bounds__(256, 4) kernelD(
    const int* __restrict__ row,
    const int* __restrict__ col,
    const float4* __restrict__ scr,
    float* __restrict__ Eo,
    int Ecount)
{
    __shared__ __align__(16) float sm[512 * 5];
    const int t = threadIdx.x;
    const int warp = t >> 5;
    const int lane = t & 31;
    const int k = lane >> 1;             // pair index 0..15
    const int h = lane & 1;              // half selector
    const int base = blockIdx.x * 512;
    const bool full = (base + 512 <= Ecount);

    if (full) {
        #pragma unroll
        for (int pass = 0; pass < 4; pass++) {
            const int eb = warp * 64 + pass * 16 + k;
            const int e  = base + eb;
            const int r = __ldcs(row + e);
            const int c = __ldcs(col + e);
            // lanes 2k,2k+1 hit adjacent float4s of one endpoint's 128B line
            // in the same instruction -> one wavefront per endpoint.
            float4 Ar = __ldg(scr + 2*r + h);
            float4 Ac = __ldg(scr + 2*c + h);
            float fa, fb = Ar.w - Ac.w;   // h=0: d_cum_dist, h=1: d_cum_msd
            if (h == 0) {
                float ddx = Ar.x - Ac.x, ddy = Ar.y - Ac.y, ddz = Ar.z - Ac.z;
                fa = sqrtf(ddx*ddx + ddy*ddy + ddz*ddz);          // d
                sm[eb*5 + 0] = (float)((r & (TRAJ-1)) - (c & (TRAJ-1))) * (1.0f / (float)TRAJ);
                sm[eb*5 + 1] = fa;
                sm[eb*5 + 3] = fb;
            } else {
                fa = Ar.x*Ac.x + Ar.y*Ac.y + Ar.z*Ac.z;           // corr
                sm[eb*5 + 2] = fa;
                sm[eb*5 + 4] = fb;
            }
        }
        __syncthreads();

        if (t == 0) {
            // order generic-proxy STS before async-proxy TMA read of smem
            asm volatile("fence.proxy.async.shared::cta;" ::: "memory");
            unsigned int s_sm = (unsigned int)__cvta_generic_to_shared(sm);
            asm volatile(
                "cp.async.bulk.global.shared::cta.bulk_group [%0], [%1], %2;"
                :: "l"(Eo + (size_t)base * 5), "r"(s_sm), "r"(10240u)
                : "memory");
            asm volatile("cp.async.bulk.commit_group;" ::: "memory");
            asm volatile("cp.async.bulk.wait_group 0;" ::: "memory");
        }
    } else {
        // tail fallback (not hit for E = 8,388,608, kept for generality)
        #pragma unroll
        for (int pass = 0; pass < 4; pass++) {
            const int eb = warp * 64 + pass * 16 + k;
            const int e  = base + eb;
            float fa = 0.f, fb = 0.f, f0 = 0.f;
            if (e < Ecount) {
                const int r = __ldcs(row + e);
                const int c = __ldcs(col + e);
                float4 Ar = __ldg(scr + 2*r + h);
                float4 Ac = __ldg(scr + 2*c + h);
                if (h == 0) {
                    float ddx = Ar.x - Ac.x, ddy = Ar.y - Ac.y, ddz = Ar.z - Ac.z;
                    fa = sqrtf(ddx*ddx + ddy*ddy + ddz*ddz);
                } else {
                    fa = Ar.x*Ac.x + Ar.y*Ac.y + Ar.z*Ac.z;
                }
                fb = Ar.w - Ac.w;
                f0 = (float)((r & (TRAJ-1)) - (c & (TRAJ-1))) * (1.0f / (float)TRAJ);
            }
            if (h == 0) {
                sm[eb*5 + 0] = f0;
                sm[eb*5 + 1] = fa;
                sm[eb*5 + 3] = fb;
            } else {
                sm[eb*5 + 2] = fa;
                sm[eb*5 + 4] = fb;
            }
        }
        __syncthreads();
        const int nvalid = Ecount - base;
        if (nvalid > 0) {
            const int nf = nvalid * 5;
            for (int j = t; j < nf; j += 256) __stcs(Eo + (size_t)base * 5 + j, sm[j]);
        }
    }
}

// ---------------------------------------------------------------------------
extern "C" void kernel_launch(void* const* d_in, const int* in_sizes, int n_in,
                              void* d_out, int out_size)
{
    const float* P   = (const float*)d_in[0];
    const int*   row = (const int*)d_in[2];
    const int*   col = (const int*)d_in[3];

    const int N = in_sizes[0] / 3;
    const int G = N / TRAJ;
    const int E = in_sizes[2];

    float* out = (float*)d_out;
    float* X  = out;                       // [N,4]
    float* Eo = out + (size_t)4 * N;       // [E,5]
    float* S  = Eo + (size_t)5 * E;        // [G,2]
    float* U  = S + (size_t)2 * G;         // [G,3]

    float4* scr;  cudaGetSymbolAddress((void**)&scr,  g_scratch);
    float2* aux;  cudaGetSymbolAddress((void**)&aux,  g_aux);
    float*  cm;   cudaGetSymbolAddress((void**)&cm,   g_cm);
    float*  gMax; cudaGetSymbolAddress((void**)&gMax, g_graphMax);
    float*  gFv;  cudaGetSymbolAddress((void**)&gFv,  g_fv);
    float*  gPfx; cudaGetSymbolAddress((void**)&gPfx, g_gpfx);

    kernelA<<<G, 128>>>(P, scr, aux, cm, S, U, gMax, gFv);
    kernelB<<<1, 1024>>>(gMax, gPfx);
    kernelC<<<N / 512, 512>>>(aux, cm, gPfx, gFv, X);
    kernelD<<<(E + 511) / 512, 256>>>(row, col, scr, Eo, E);
}